// round 15
// baseline (speedup 1.0000x reference)
#include <cuda_runtime.h>
#include <cuda_fp16.h>
#include <math.h>
#include <stdint.h>

#define T_TOK 2048
#define D_MODEL 1024
#define D_FF 4096
#define N_EXP 8

// ---------------- static scratch (no allocations allowed) ----------------
__device__ __half g_Hh[(size_t)N_EXP * T_TOK * D_FF];       // half activations [e][pos][ff]
__device__ __half g_Xh[(size_t)N_EXP * T_TOK * D_MODEL];    // gathered X rows, half
__device__ __half g_W1h[(size_t)N_EXP * D_MODEL * D_FF];    // w1 as-is: [e][k=d][n=ff], half
__device__ __half g_W2h[(size_t)N_EXP * D_FF * D_MODEL];    // w2 as-is: [e][k=ff][n=d], half
__device__ float  g_Y[(size_t)2 * T_TOK * D_MODEL];
__device__ int    g_alist[N_EXP * T_TOK];
__device__ float  g_wlist[N_EXP * T_TOK];
__device__ int    g_count[N_EXP];

// ---------------- helpers ----------------
__device__ __forceinline__ void cp16(uint32_t dst, const void* src) {
    asm volatile("cp.async.cg.shared.global [%0], [%1], 16;"
                 :: "r"(dst), "l"(src) : "memory");
}
__device__ __forceinline__ uint32_t smem_u32(const void* p) {
    uint32_t a;
    asm("{ .reg .u64 t; cvta.to.shared.u64 t, %1; cvt.u32.u64 %0, t; }"
        : "=r"(a) : "l"(p));
    return a;
}
__device__ __forceinline__ void ldsm4(uint32_t& r0, uint32_t& r1, uint32_t& r2, uint32_t& r3,
                                      uint32_t addr) {
    asm volatile("ldmatrix.sync.aligned.m8n8.x4.shared.b16 {%0,%1,%2,%3}, [%4];"
                 : "=r"(r0), "=r"(r1), "=r"(r2), "=r"(r3) : "r"(addr));
}
__device__ __forceinline__ void ldsm4t(uint32_t& r0, uint32_t& r1, uint32_t& r2, uint32_t& r3,
                                       uint32_t addr) {
    asm volatile("ldmatrix.sync.aligned.m8n8.x4.trans.shared.b16 {%0,%1,%2,%3}, [%4];"
                 : "=r"(r0), "=r"(r1), "=r"(r2), "=r"(r3) : "r"(addr));
}
__device__ __forceinline__ void mma16(float* c, const uint32_t* a, const uint32_t* b) {
    asm volatile(
        "mma.sync.aligned.m16n8k16.row.col.f32.f16.f16.f32 "
        "{%0,%1,%2,%3},{%4,%5,%6,%7},{%8,%9},{%0,%1,%2,%3};"
        : "+f"(c[0]), "+f"(c[1]), "+f"(c[2]), "+f"(c[3])
        : "r"(a[0]), "r"(a[1]), "r"(a[2]), "r"(a[3]), "r"(b[0]), "r"(b[1]));
}

// ---------------- small kernels ----------------
__global__ void zero_counts_kernel() {
    int i = threadIdx.x;
    if (i < N_EXP) g_count[i] = 0;
}

__global__ void gate_kernel(const float* __restrict__ x,
                            const float* __restrict__ wg,
                            const float* __restrict__ bg) {
    int warp = (blockIdx.x * blockDim.x + threadIdx.x) >> 5;
    int lane = threadIdx.x & 31;
    if (warp >= T_TOK) return;

    const float* xr = x + (size_t)warp * D_MODEL;
    float acc[N_EXP];
#pragma unroll
    for (int e = 0; e < N_EXP; e++) acc[e] = 0.f;
    for (int d = lane; d < D_MODEL; d += 32) {
        float xv = xr[d];
        const float* wr = wg + (size_t)d * N_EXP;
#pragma unroll
        for (int e = 0; e < N_EXP; e++) acc[e] += xv * wr[e];
    }
#pragma unroll
    for (int e = 0; e < N_EXP; e++) {
#pragma unroll
        for (int off = 16; off > 0; off >>= 1)
            acc[e] += __shfl_xor_sync(0xFFFFFFFFu, acc[e], off);
    }
    if (lane == 0) {
        float v[N_EXP];
#pragma unroll
        for (int e = 0; e < N_EXP; e++) v[e] = acc[e] + bg[e];
        int i0 = 0;
#pragma unroll
        for (int e = 1; e < N_EXP; e++) if (v[e] > v[i0]) i0 = e;
        int i1 = (i0 == 0) ? 1 : 0;
#pragma unroll
        for (int e = 0; e < N_EXP; e++)
            if (e != i0 && v[e] > v[i1]) i1 = e;
        float w0 = 1.0f / (1.0f + expf(v[i1] - v[i0]));
        float w1 = 1.0f - w0;
        int p0 = atomicAdd(&g_count[i0], 1);
        g_alist[i0 * T_TOK + p0] = warp * 2 + 0;
        g_wlist[i0 * T_TOK + p0] = w0;
        int p1 = atomicAdd(&g_count[i1], 1);
        g_alist[i1 * T_TOK + p1] = warp * 2 + 1;
        g_wlist[i1 * T_TOK + p1] = w1;
    }
}

// gather + convert to half
__global__ void gather_kernel(const float* __restrict__ x) {
    int pos = blockIdx.x;
    int e = blockIdx.y;
    if (pos >= g_count[e]) return;
    int tok = g_alist[e * T_TOK + pos] >> 1;
    const float4* src = (const float4*)(x + (size_t)tok * D_MODEL);
    float4 v = src[threadIdx.x];
    __half2* dst = (__half2*)(g_Xh + ((size_t)e * T_TOK + pos) * D_MODEL) + threadIdx.x * 2;
    dst[0] = __floats2half2_rn(v.x, v.y);
    dst[1] = __floats2half2_rn(v.z, v.w);
}

// streaming f32 -> f16 convert (no transpose)
__global__ void __launch_bounds__(256) conv_kernel(const float4* __restrict__ in,
                                                   __half2* __restrict__ out, int n4) {
    int i = blockIdx.x * blockDim.x + threadIdx.x;
    if (i >= n4) return;
    float4 v = in[i];
    out[2 * i + 0] = __floats2half2_rn(v.x, v.y);
    out[2 * i + 1] = __floats2half2_rn(v.z, v.w);
}

// ---------------- fp16 mma.sync grouped GEMM (ldmatrix fragments) ----------------
// CTA 128x128, BK=64, 4 warps (2x2 grid of 64x64 warp tiles), 3-stage cp.async,
// 2 CTAs/SM. A smem [m][k] pitch 144B (9x16B units); B smem [k][n] pitch 272B
// (17 units) read via ldmatrix.trans. Both conflict-free by pitch.
#define BM 128
#define BN 128
#define BK 64
#define STAGES 3
#define A_PITCH 144                      // bytes per A row (64 halfs + pad)
#define B_PITCH 272                      // bytes per B k-row (128 halfs + pad)
#define A_TILE_B (BM * A_PITCH)          // 18432
#define B_TILE_B (BK * B_PITCH)          // 17408
#define BUF_B (A_TILE_B + B_TILE_B)      // 35840
#define SMEM_DYN (STAGES * BUF_B)        // 107520
#define NTHREADS 128

// MODE 0: Hh = half(relu(Xh @ w1 + b1))   (K=1024, NW=4096, B=g_W1h)
// MODE 1: Y  = wgt * (Hh @ w2 + b2)       (K=4096, NW=1024, B=g_W2h)
template <int MODE>
__global__ void __launch_bounds__(NTHREADS, 2) moe_gemm(const __half* __restrict__ Wh,
                                                        const float* __restrict__ bias) {
    constexpr int K  = MODE ? D_FF : D_MODEL;
    constexpr int NW = MODE ? D_MODEL : D_FF;
    constexpr int NC = K / BK;

    int e = blockIdx.z;
    int cnt = g_count[e];
    int m0 = blockIdx.y * BM;
    if (m0 >= cnt) return;
    int n0 = blockIdx.x * BN;

    const __half* A  = (MODE ? g_Hh : g_Xh) + ((size_t)e * T_TOK + m0) * K;
    const __half* Bw = Wh + (size_t)e * K * NW + n0;

    extern __shared__ __align__(16) __half sm_h[];
    uint32_t sb = smem_u32(sm_h);

    int tid = threadIdx.x, lane = tid & 31, wid = tid >> 5;
    int wm = (wid >> 1) * 64;
    int wn = (wid & 1) * 64;
    int grp = lane >> 2;        // epilogue row within 8-group
    int c2  = (lane & 3) * 2;   // epilogue col pair

    // ldmatrix lane addressing
    int which = lane >> 3;      // 0..3
    int lr    = lane & 7;       // row within 8x8 tile
    // A x4: matrix w: row = wm + mt*16 + (w&1)*8 + lr, colhalf = s*16 + (w>>1)*8
    uint32_t aLane = (uint32_t)(wm + (which & 1) * 8 + lr) * A_PITCH
                   + (uint32_t)(which >> 1) * 16;
    // B x4.trans: matrix w: k-row = s*16 + (w&1)*8 + lr, n = wn + pair*16 + (w>>1)*8
    uint32_t bLane = (uint32_t)((which & 1) * 8 + lr) * B_PITCH
                   + (uint32_t)(wn + (which >> 1) * 8) * 2;

    // A: 128 rows x 8 units = 1024; B: 64 k-rows x 16 units = 1024
    auto load_chunk = [&](int c, int p) {
        uint32_t sA = sb + (uint32_t)p * BUF_B;
        uint32_t sB = sA + A_TILE_B;
        int k0 = c * BK;
#pragma unroll
        for (int i = 0; i < 8; i++) {
            int idx = i * NTHREADS + tid;
            int m = idx >> 3, u = idx & 7;
            cp16(sA + (uint32_t)m * A_PITCH + (uint32_t)u * 16,
                 A + (size_t)m * K + k0 + u * 8);
        }
#pragma unroll
        for (int i = 0; i < 8; i++) {
            int idx = i * NTHREADS + tid;
            int k = idx >> 4, u = idx & 15;
            cp16(sB + (uint32_t)k * B_PITCH + (uint32_t)u * 16,
                 Bw + (size_t)(k0 + k) * NW + u * 8);
        }
        asm volatile("cp.async.commit_group;" ::: "memory");
    };

    float acc[4][8][4];
#pragma unroll
    for (int mt = 0; mt < 4; mt++)
#pragma unroll
        for (int nt = 0; nt < 8; nt++)
#pragma unroll
            for (int q = 0; q < 4; q++) acc[mt][nt][q] = 0.f;

    load_chunk(0, 0);
    load_chunk(1, 1);

    for (int c = 0; c < NC; c++) {
        if (c + 1 < NC) asm volatile("cp.async.wait_group 1;" ::: "memory");
        else            asm volatile("cp.async.wait_group 0;" ::: "memory");
        __syncthreads();
        if (c + 2 < NC) load_chunk(c + 2, (c + 2) % STAGES);

        uint32_t stA = sb + (uint32_t)(c % STAGES) * BUF_B + aLane;
        uint32_t stB = sb + (uint32_t)(c % STAGES) * BUF_B + A_TILE_B + bLane;

#pragma unroll
        for (int s = 0; s < 4; s++) {          // k16 steps within BK=64
            uint32_t aS = stA + (uint32_t)s * 32;            // +16 halfs
            uint32_t bS = stB + (uint32_t)s * (16 * B_PITCH);
            uint32_t af[4][4];
#pragma unroll
            for (int mt = 0; mt < 4; mt++)
                ldsm4(af[mt][0], af[mt][1], af[mt][2], af[mt][3],
                      aS + (uint32_t)mt * (16 * A_PITCH));
            uint32_t bf[8][2];
#pragma unroll
            for (int p = 0; p < 4; p++)
                ldsm4t(bf[2 * p][0], bf[2 * p][1], bf[2 * p + 1][0], bf[2 * p + 1][1],
                       bS + (uint32_t)p * 32);               // +16 n-halfs
#pragma unroll
            for (int mt = 0; mt < 4; mt++)
#pragma unroll
                for (int nt = 0; nt < 8; nt++)
                    mma16(acc[mt][nt], af[mt], bf[nt]);
        }
    }

    // ---- epilogue (fragment layout unchanged) ----
    const float* be = bias + (size_t)e * NW;
#pragma unroll
    for (int mt = 0; mt < 4; mt++) {
        int r0 = m0 + wm + mt * 16 + grp;
        int r1 = r0 + 8;
        bool v0 = r0 < cnt, v1 = r1 < cnt;
        int aid0 = 0, aid1 = 0;
        float wg0 = 0.f, wg1 = 0.f;
        if (MODE == 1) {
            if (v0) { aid0 = g_alist[e * T_TOK + r0]; wg0 = g_wlist[e * T_TOK + r0]; }
            if (v1) { aid1 = g_alist[e * T_TOK + r1]; wg1 = g_wlist[e * T_TOK + r1]; }
        }
#pragma unroll
        for (int nt = 0; nt < 8; nt++) {
            int n = n0 + wn + nt * 8 + c2;
            float2 b2 = *(const float2*)(be + n);
            float* cc = acc[mt][nt];
            if (v0) {
                float x0 = cc[0] + b2.x, x1 = cc[1] + b2.y;
                if (MODE == 0) {
                    x0 = x0 > 0.f ? x0 : 0.f;
                    x1 = x1 > 0.f ? x1 : 0.f;
                    *(__half2*)(g_Hh + ((size_t)e * T_TOK + r0) * D_FF + n) =
                        __floats2half2_rn(x0, x1);
                } else {
                    float2 o; o.x = x0 * wg0; o.y = x1 * wg0;
                    *(float2*)(g_Y + (size_t)aid0 * D_MODEL + n) = o;
                }
            }
            if (v1) {
                float x2 = cc[2] + b2.x, x3 = cc[3] + b2.y;
                if (MODE == 0) {
                    x2 = x2 > 0.f ? x2 : 0.f;
                    x3 = x3 > 0.f ? x3 : 0.f;
                    *(__half2*)(g_Hh + ((size_t)e * T_TOK + r1) * D_FF + n) =
                        __floats2half2_rn(x2, x3);
                } else {
                    float2 o; o.x = x2 * wg1; o.y = x3 * wg1;
                    *(float2*)(g_Y + (size_t)aid1 * D_MODEL + n) = o;
                }
            }
        }
    }
}

// ---------------- combine: out[t] = Y[2t] + Y[2t+1] ----------------
__global__ void combine_kernel(float* __restrict__ out) {
    int i = blockIdx.x * blockDim.x + threadIdx.x;
    int total = T_TOK * D_MODEL / 4;
    if (i >= total) return;
    int t = (i * 4) >> 10;
    const float4* y0 = (const float4*)(g_Y + (size_t)(2 * t) * D_MODEL) + (i & 255);
    const float4* y1 = (const float4*)(g_Y + (size_t)(2 * t + 1) * D_MODEL) + (i & 255);
    float4 a = *y0, b = *y1;
    float4 r;
    r.x = a.x + b.x; r.y = a.y + b.y; r.z = a.z + b.z; r.w = a.w + b.w;
    ((float4*)out)[i] = r;
}

// ---------------- launch ----------------
extern "C" void kernel_launch(void* const* d_in, const int* in_sizes, int n_in,
                              void* d_out, int out_size) {
    const float* x   = (const float*)d_in[0];
    const float* wg  = (const float*)d_in[1];
    const float* bg  = (const float*)d_in[2];
    const float* w1  = (const float*)d_in[3];
    const float* b1  = (const float*)d_in[4];
    const float* w2  = (const float*)d_in[5];
    const float* b2  = (const float*)d_in[6];
    float* out = (float*)d_out;

    cudaFuncSetAttribute(moe_gemm<0>, cudaFuncAttributeMaxDynamicSharedMemorySize, SMEM_DYN);
    cudaFuncSetAttribute(moe_gemm<1>, cudaFuncAttributeMaxDynamicSharedMemorySize, SMEM_DYN);

    __half* w1h; cudaGetSymbolAddress((void**)&w1h, g_W1h);
    __half* w2h; cudaGetSymbolAddress((void**)&w2h, g_W2h);

    zero_counts_kernel<<<1, 32>>>();
    gate_kernel<<<(T_TOK * 32) / 256, 256>>>(x, wg, bg);

    // streaming weight converts (no transpose needed with ldmatrix.trans)
    int n4 = (N_EXP * D_MODEL * D_FF) / 4;   // 8388608 float4 per weight tensor
    conv_kernel<<<(n4 + 255) / 256, 256>>>((const float4*)w1, (__half2*)w1h, n4);
    conv_kernel<<<(n4 + 255) / 256, 256>>>((const float4*)w2, (__half2*)w2h, n4);

    dim3 gg(T_TOK, N_EXP);
    gather_kernel<<<gg, 256>>>(x);

    dim3 g1(D_FF / BN, T_TOK / BM, N_EXP);     // 32 x 16 x 8
    moe_gemm<0><<<g1, NTHREADS, SMEM_DYN>>>(w1h, b1);

    dim3 g2(D_MODEL / BN, T_TOK / BM, N_EXP);  // 8 x 16 x 8
    moe_gemm<1><<<g2, NTHREADS, SMEM_DYN>>>(w2h, b2);

    combine_kernel<<<(T_TOK * D_MODEL / 4 + 255) / 256, 256>>>(out);
}

// round 16
// speedup vs baseline: 1.0121x; 1.0121x over previous
#include <cuda_runtime.h>
#include <cuda_fp16.h>
#include <math.h>
#include <stdint.h>

#define T_TOK 2048
#define D_MODEL 1024
#define D_FF 4096
#define N_EXP 8

// ---------------- static scratch (no allocations allowed) ----------------
__device__ __half g_Hh[(size_t)N_EXP * T_TOK * D_FF];       // half activations [e][pos][ff]
__device__ __half g_Xh[(size_t)N_EXP * T_TOK * D_MODEL];    // gathered X rows, half
__device__ __half g_W1h[(size_t)N_EXP * D_MODEL * D_FF];    // w1 as-is: [e][k=d][n=ff], half
__device__ __half g_W2h[(size_t)N_EXP * D_FF * D_MODEL];    // w2 as-is: [e][k=ff][n=d], half
__device__ float  g_Y[(size_t)2 * T_TOK * D_MODEL];
__device__ int    g_alist[N_EXP * T_TOK];
__device__ float  g_wlist[N_EXP * T_TOK];
__device__ int    g_count[N_EXP];

// ---------------- helpers ----------------
__device__ __forceinline__ void cp16(uint32_t dst, const void* src) {
    asm volatile("cp.async.cg.shared.global [%0], [%1], 16;"
                 :: "r"(dst), "l"(src) : "memory");
}
__device__ __forceinline__ uint32_t smem_u32(const void* p) {
    uint32_t a;
    asm("{ .reg .u64 t; cvta.to.shared.u64 t, %1; cvt.u32.u64 %0, t; }"
        : "=r"(a) : "l"(p));
    return a;
}
__device__ __forceinline__ void ldsm4(uint32_t& r0, uint32_t& r1, uint32_t& r2, uint32_t& r3,
                                      uint32_t addr) {
    asm volatile("ldmatrix.sync.aligned.m8n8.x4.shared.b16 {%0,%1,%2,%3}, [%4];"
                 : "=r"(r0), "=r"(r1), "=r"(r2), "=r"(r3) : "r"(addr));
}
__device__ __forceinline__ void ldsm4t(uint32_t& r0, uint32_t& r1, uint32_t& r2, uint32_t& r3,
                                       uint32_t addr) {
    asm volatile("ldmatrix.sync.aligned.m8n8.x4.trans.shared.b16 {%0,%1,%2,%3}, [%4];"
                 : "=r"(r0), "=r"(r1), "=r"(r2), "=r"(r3) : "r"(addr));
}
__device__ __forceinline__ void mma16(float* c, const uint32_t* a, const uint32_t* b) {
    asm volatile(
        "mma.sync.aligned.m16n8k16.row.col.f32.f16.f16.f32 "
        "{%0,%1,%2,%3},{%4,%5,%6,%7},{%8,%9},{%0,%1,%2,%3};"
        : "+f"(c[0]), "+f"(c[1]), "+f"(c[2]), "+f"(c[3])
        : "r"(a[0]), "r"(a[1]), "r"(a[2]), "r"(a[3]), "r"(b[0]), "r"(b[1]));
}

// ---------------- small kernels ----------------
__global__ void zero_counts_kernel() {
    int i = threadIdx.x;
    if (i < N_EXP) g_count[i] = 0;
}

__global__ void gate_kernel(const float* __restrict__ x,
                            const float* __restrict__ wg,
                            const float* __restrict__ bg) {
    int warp = (blockIdx.x * blockDim.x + threadIdx.x) >> 5;
    int lane = threadIdx.x & 31;
    if (warp >= T_TOK) return;

    const float* xr = x + (size_t)warp * D_MODEL;
    float acc[N_EXP];
#pragma unroll
    for (int e = 0; e < N_EXP; e++) acc[e] = 0.f;
    for (int d = lane; d < D_MODEL; d += 32) {
        float xv = xr[d];
        const float* wr = wg + (size_t)d * N_EXP;
#pragma unroll
        for (int e = 0; e < N_EXP; e++) acc[e] += xv * wr[e];
    }
#pragma unroll
    for (int e = 0; e < N_EXP; e++) {
#pragma unroll
        for (int off = 16; off > 0; off >>= 1)
            acc[e] += __shfl_xor_sync(0xFFFFFFFFu, acc[e], off);
    }
    if (lane == 0) {
        float v[N_EXP];
#pragma unroll
        for (int e = 0; e < N_EXP; e++) v[e] = acc[e] + bg[e];
        int i0 = 0;
#pragma unroll
        for (int e = 1; e < N_EXP; e++) if (v[e] > v[i0]) i0 = e;
        int i1 = (i0 == 0) ? 1 : 0;
#pragma unroll
        for (int e = 0; e < N_EXP; e++)
            if (e != i0 && v[e] > v[i1]) i1 = e;
        float w0 = 1.0f / (1.0f + expf(v[i1] - v[i0]));
        float w1 = 1.0f - w0;
        int p0 = atomicAdd(&g_count[i0], 1);
        g_alist[i0 * T_TOK + p0] = warp * 2 + 0;
        g_wlist[i0 * T_TOK + p0] = w0;
        int p1 = atomicAdd(&g_count[i1], 1);
        g_alist[i1 * T_TOK + p1] = warp * 2 + 1;
        g_wlist[i1 * T_TOK + p1] = w1;
    }
}

// gather + convert to half
__global__ void gather_kernel(const float* __restrict__ x) {
    int pos = blockIdx.x;
    int e = blockIdx.y;
    if (pos >= g_count[e]) return;
    int tok = g_alist[e * T_TOK + pos] >> 1;
    const float4* src = (const float4*)(x + (size_t)tok * D_MODEL);
    float4 v = src[threadIdx.x];
    __half2* dst = (__half2*)(g_Xh + ((size_t)e * T_TOK + pos) * D_MODEL) + threadIdx.x * 2;
    dst[0] = __floats2half2_rn(v.x, v.y);
    dst[1] = __floats2half2_rn(v.z, v.w);
}

// streaming f32 -> f16 convert (no transpose)
__global__ void __launch_bounds__(256) conv_kernel(const float4* __restrict__ in,
                                                   __half2* __restrict__ out, int n4) {
    int i = blockIdx.x * blockDim.x + threadIdx.x;
    if (i >= n4) return;
    float4 v = in[i];
    out[2 * i + 0] = __floats2half2_rn(v.x, v.y);
    out[2 * i + 1] = __floats2half2_rn(v.z, v.w);
}

// ---------------- fp16 mma.sync grouped GEMM (ldmatrix fragments) ----------------
// CTA 128x128, BK=64, 4 warps (2x2 grid of 64x64 warp tiles), 3-stage cp.async,
// 2 CTAs/SM. A smem [m][k] pitch 144B (9x16B units); B smem [k][n] pitch 272B
// (17 units) read via ldmatrix.trans. Both conflict-free by pitch.
#define BM 128
#define BN 128
#define BK 64
#define STAGES 3
#define A_PITCH 144                      // bytes per A row (64 halfs + pad)
#define B_PITCH 272                      // bytes per B k-row (128 halfs + pad)
#define A_TILE_B (BM * A_PITCH)          // 18432
#define B_TILE_B (BK * B_PITCH)          // 17408
#define BUF_B (A_TILE_B + B_TILE_B)      // 35840
#define SMEM_DYN (STAGES * BUF_B)        // 107520
#define NTHREADS 128

// MODE 0: Hh = half(relu(Xh @ w1 + b1))   (K=1024, NW=4096, B=g_W1h)
// MODE 1: Y  = wgt * (Hh @ w2 + b2)       (K=4096, NW=1024, B=g_W2h)
template <int MODE>
__global__ void __launch_bounds__(NTHREADS, 2) moe_gemm(const __half* __restrict__ Wh,
                                                        const float* __restrict__ bias) {
    constexpr int K  = MODE ? D_FF : D_MODEL;
    constexpr int NW = MODE ? D_MODEL : D_FF;
    constexpr int NC = K / BK;

    int e = blockIdx.z;
    int cnt = g_count[e];
    int m0 = blockIdx.y * BM;
    if (m0 >= cnt) return;
    int n0 = blockIdx.x * BN;

    const __half* A  = (MODE ? g_Hh : g_Xh) + ((size_t)e * T_TOK + m0) * K;
    const __half* Bw = Wh + (size_t)e * K * NW + n0;

    extern __shared__ __align__(16) __half sm_h[];
    uint32_t sb = smem_u32(sm_h);

    int tid = threadIdx.x, lane = tid & 31, wid = tid >> 5;
    int wm = (wid >> 1) * 64;
    int wn = (wid & 1) * 64;
    int grp = lane >> 2;        // epilogue row within 8-group
    int c2  = (lane & 3) * 2;   // epilogue col pair

    // ldmatrix lane addressing
    int which = lane >> 3;      // 0..3
    int lr    = lane & 7;       // row within 8x8 tile
    // A x4: matrix w: row = wm + mt*16 + (w&1)*8 + lr, colhalf = s*16 + (w>>1)*8
    uint32_t aLane = (uint32_t)(wm + (which & 1) * 8 + lr) * A_PITCH
                   + (uint32_t)(which >> 1) * 16;
    // B x4.trans: matrix w: k-row = s*16 + (w&1)*8 + lr, n = wn + pair*16 + (w>>1)*8
    uint32_t bLane = (uint32_t)((which & 1) * 8 + lr) * B_PITCH
                   + (uint32_t)(wn + (which >> 1) * 8) * 2;

    // A: 128 rows x 8 units = 1024; B: 64 k-rows x 16 units = 1024
    auto load_chunk = [&](int c, int p) {
        uint32_t sA = sb + (uint32_t)p * BUF_B;
        uint32_t sB = sA + A_TILE_B;
        int k0 = c * BK;
#pragma unroll
        for (int i = 0; i < 8; i++) {
            int idx = i * NTHREADS + tid;
            int m = idx >> 3, u = idx & 7;
            cp16(sA + (uint32_t)m * A_PITCH + (uint32_t)u * 16,
                 A + (size_t)m * K + k0 + u * 8);
        }
#pragma unroll
        for (int i = 0; i < 8; i++) {
            int idx = i * NTHREADS + tid;
            int k = idx >> 4, u = idx & 15;
            cp16(sB + (uint32_t)k * B_PITCH + (uint32_t)u * 16,
                 Bw + (size_t)(k0 + k) * NW + u * 8);
        }
        asm volatile("cp.async.commit_group;" ::: "memory");
    };

    float acc[4][8][4];
#pragma unroll
    for (int mt = 0; mt < 4; mt++)
#pragma unroll
        for (int nt = 0; nt < 8; nt++)
#pragma unroll
            for (int q = 0; q < 4; q++) acc[mt][nt][q] = 0.f;

    load_chunk(0, 0);
    load_chunk(1, 1);

    for (int c = 0; c < NC; c++) {
        if (c + 1 < NC) asm volatile("cp.async.wait_group 1;" ::: "memory");
        else            asm volatile("cp.async.wait_group 0;" ::: "memory");
        __syncthreads();
        if (c + 2 < NC) load_chunk(c + 2, (c + 2) % STAGES);

        uint32_t stA = sb + (uint32_t)(c % STAGES) * BUF_B + aLane;
        uint32_t stB = sb + (uint32_t)(c % STAGES) * BUF_B + A_TILE_B + bLane;

#pragma unroll
        for (int s = 0; s < 4; s++) {          // k16 steps within BK=64
            uint32_t aS = stA + (uint32_t)s * 32;            // +16 halfs
            uint32_t bS = stB + (uint32_t)s * (16 * B_PITCH);
            uint32_t af[4][4];
#pragma unroll
            for (int mt = 0; mt < 4; mt++)
                ldsm4(af[mt][0], af[mt][1], af[mt][2], af[mt][3],
                      aS + (uint32_t)mt * (16 * A_PITCH));
            uint32_t bf[8][2];
#pragma unroll
            for (int p = 0; p < 4; p++)
                ldsm4t(bf[2 * p][0], bf[2 * p][1], bf[2 * p + 1][0], bf[2 * p + 1][1],
                       bS + (uint32_t)p * 32);               // +16 n-halfs
#pragma unroll
            for (int mt = 0; mt < 4; mt++)
#pragma unroll
                for (int nt = 0; nt < 8; nt++)
                    mma16(acc[mt][nt], af[mt], bf[nt]);
        }
    }

    // ---- epilogue (fragment layout unchanged) ----
    const float* be = bias + (size_t)e * NW;
#pragma unroll
    for (int mt = 0; mt < 4; mt++) {
        int r0 = m0 + wm + mt * 16 + grp;
        int r1 = r0 + 8;
        bool v0 = r0 < cnt, v1 = r1 < cnt;
        int aid0 = 0, aid1 = 0;
        float wg0 = 0.f, wg1 = 0.f;
        if (MODE == 1) {
            if (v0) { aid0 = g_alist[e * T_TOK + r0]; wg0 = g_wlist[e * T_TOK + r0]; }
            if (v1) { aid1 = g_alist[e * T_TOK + r1]; wg1 = g_wlist[e * T_TOK + r1]; }
        }
#pragma unroll
        for (int nt = 0; nt < 8; nt++) {
            int n = n0 + wn + nt * 8 + c2;
            float2 b2 = *(const float2*)(be + n);
            float* cc = acc[mt][nt];
            if (v0) {
                float x0 = cc[0] + b2.x, x1 = cc[1] + b2.y;
                if (MODE == 0) {
                    x0 = x0 > 0.f ? x0 : 0.f;
                    x1 = x1 > 0.f ? x1 : 0.f;
                    *(__half2*)(g_Hh + ((size_t)e * T_TOK + r0) * D_FF + n) =
                        __floats2half2_rn(x0, x1);
                } else {
                    float2 o; o.x = x0 * wg0; o.y = x1 * wg0;
                    *(float2*)(g_Y + (size_t)aid0 * D_MODEL + n) = o;
                }
            }
            if (v1) {
                float x2 = cc[2] + b2.x, x3 = cc[3] + b2.y;
                if (MODE == 0) {
                    x2 = x2 > 0.f ? x2 : 0.f;
                    x3 = x3 > 0.f ? x3 : 0.f;
                    *(__half2*)(g_Hh + ((size_t)e * T_TOK + r1) * D_FF + n) =
                        __floats2half2_rn(x2, x3);
                } else {
                    float2 o; o.x = x2 * wg1; o.y = x3 * wg1;
                    *(float2*)(g_Y + (size_t)aid1 * D_MODEL + n) = o;
                }
            }
        }
    }
}

// ---------------- combine: out[t] = Y[2t] + Y[2t+1] ----------------
__global__ void combine_kernel(float* __restrict__ out) {
    int i = blockIdx.x * blockDim.x + threadIdx.x;
    int total = T_TOK * D_MODEL / 4;
    if (i >= total) return;
    int t = (i * 4) >> 10;
    const float4* y0 = (const float4*)(g_Y + (size_t)(2 * t) * D_MODEL) + (i & 255);
    const float4* y1 = (const float4*)(g_Y + (size_t)(2 * t + 1) * D_MODEL) + (i & 255);
    float4 a = *y0, b = *y1;
    float4 r;
    r.x = a.x + b.x; r.y = a.y + b.y; r.z = a.z + b.z; r.w = a.w + b.w;
    ((float4*)out)[i] = r;
}

// ---------------- launch ----------------
extern "C" void kernel_launch(void* const* d_in, const int* in_sizes, int n_in,
                              void* d_out, int out_size) {
    const float* x   = (const float*)d_in[0];
    const float* wg  = (const float*)d_in[1];
    const float* bg  = (const float*)d_in[2];
    const float* w1  = (const float*)d_in[3];
    const float* b1  = (const float*)d_in[4];
    const float* w2  = (const float*)d_in[5];
    const float* b2  = (const float*)d_in[6];
    float* out = (float*)d_out;

    cudaFuncSetAttribute(moe_gemm<0>, cudaFuncAttributeMaxDynamicSharedMemorySize, SMEM_DYN);
    cudaFuncSetAttribute(moe_gemm<1>, cudaFuncAttributeMaxDynamicSharedMemorySize, SMEM_DYN);

    __half* w1h; cudaGetSymbolAddress((void**)&w1h, g_W1h);
    __half* w2h; cudaGetSymbolAddress((void**)&w2h, g_W2h);

    zero_counts_kernel<<<1, 32>>>();
    gate_kernel<<<(T_TOK * 32) / 256, 256>>>(x, wg, bg);

    // streaming weight converts (no transpose needed with ldmatrix.trans)
    int n4 = (N_EXP * D_MODEL * D_FF) / 4;   // 8388608 float4 per weight tensor
    conv_kernel<<<(n4 + 255) / 256, 256>>>((const float4*)w1, (__half2*)w1h, n4);
    conv_kernel<<<(n4 + 255) / 256, 256>>>((const float4*)w2, (__half2*)w2h, n4);

    dim3 gg(T_TOK, N_EXP);
    gather_kernel<<<gg, 256>>>(x);

    dim3 g1(D_FF / BN, T_TOK / BM, N_EXP);     // 32 x 16 x 8
    moe_gemm<0><<<g1, NTHREADS, SMEM_DYN>>>(w1h, b1);

    dim3 g2(D_MODEL / BN, T_TOK / BM, N_EXP);  // 8 x 16 x 8
    moe_gemm<1><<<g2, NTHREADS, SMEM_DYN>>>(w2h, b2);

    combine_kernel<<<(T_TOK * D_MODEL / 4 + 255) / 256, 256>>>(out);
}